// round 5
// baseline (speedup 1.0000x reference)
#include <cuda_runtime.h>
#include <cstdint>

// ---------------------------------------------------------------------------
// FrameConsistencyLoss: MSE between per-row expert projections of a and b.
//
// loss = mean over (N,64) of (a @ W[ea] + bias[ea] - b @ W[eb] - bias[eb])^2
//
// Expanded per row via precomputed 14x14 Gram tables (16 (ea,eb) pairs):
//   L = a^T G[ea,ea] a - 2 a^T G[ea,eb] b + b^T G[eb,eb] b
//       + 2 a.u[p] - 2 b.v[p] + s[p]
// Main kernel: per-block counting sort of a 1024-row tile into the 16 pairs,
// then warps process pair-uniform 32-row chunks (table loads = broadcast LDS,
// math = packed f32x2 FMA).
// ---------------------------------------------------------------------------

#define TILE  1024
#define NTHR  512
#define NWARP (NTHR / 32)

// Flat precomputed table layout (floats):
#define G_OFF 0            // 16 * 196  (G[p][i][j], row-major 14x14)
#define U_OFF 3136         // 16 * 14
#define V_OFF 3360         // 16 * 14
#define S_OFF 3584         // 16
#define TAB_F 3600

__device__ float  g_tab[TAB_F];
__device__ double g_sum;

typedef unsigned long long ull;

__device__ __forceinline__ ull pk2(float lo, float hi) {
    ull r; asm("mov.b64 %0, {%1,%2};" : "=l"(r) : "f"(lo), "f"(hi)); return r;
}
__device__ __forceinline__ void upk2(ull v, float& lo, float& hi) {
    asm("mov.b64 {%0,%1}, %2;" : "=f"(lo), "=f"(hi) : "l"(v));
}
__device__ __forceinline__ ull ffma2(ull a, ull b, ull c) {
    ull d; asm("fma.rn.f32x2 %0, %1, %2, %3;" : "=l"(d) : "l"(a), "l"(b), "l"(c)); return d;
}
__device__ __forceinline__ ull fmul2(ull a, ull b) {
    ull d; asm("mul.rn.f32x2 %0, %1, %2;" : "=l"(d) : "l"(a), "l"(b)); return d;
}

// x^T G y.  G: 14x14 row-major, viewed as [14][7] packed column-pairs (ull).
// t[j] = sum_i x_i * G[i][2j..2j+1]  (f32x2), then dot with y.
__device__ __forceinline__ float quadform(const ull* __restrict__ G,
                                          const float* __restrict__ x,
                                          const float* __restrict__ y) {
    ull t[7];
    ull xd = pk2(x[0], x[0]);
#pragma unroll
    for (int j = 0; j < 7; j++) t[j] = fmul2(G[j], xd);
#pragma unroll
    for (int i = 1; i < 14; i++) {
        xd = pk2(x[i], x[i]);
        const ull* Gi = G + i * 7;
#pragma unroll
        for (int j = 0; j < 7; j++) t[j] = ffma2(Gi[j], xd, t[j]);
    }
    float s = 0.f;
#pragma unroll
    for (int j = 0; j < 7; j++) {
        float lo, hi; upk2(t[j], lo, hi);
        s = fmaf(y[2 * j], lo, s);
        s = fmaf(y[2 * j + 1], hi, s);
    }
    return s;
}

// ---------------------------------------------------------------------------

__global__ void init_kernel() { g_sum = 0.0; }

// W: [4][14][64], B: [4][64]
__global__ void prep_kernel(const float* __restrict__ W, const float* __restrict__ B) {
    int idx = blockIdx.x * blockDim.x + threadIdx.x;
    const int total = TAB_F;
    for (; idx < total; idx += gridDim.x * blockDim.x) {
        if (idx < U_OFF) {
            int p = idx / 196, r = idx % 196, i = r / 14, j = r % 14;
            int ea = p >> 2, eb = p & 3;
            const float* wa = W + ea * 896 + i * 64;
            const float* wb = W + eb * 896 + j * 64;
            float s = 0.f;
            for (int c = 0; c < 64; c++) s = fmaf(wa[c], wb[c], s);
            g_tab[idx] = s;
        } else if (idx < V_OFF) {
            int k = idx - U_OFF; int p = k / 14, i = k % 14;
            int ea = p >> 2, eb = p & 3;
            const float* wa = W + ea * 896 + i * 64;
            float s = 0.f;
            for (int c = 0; c < 64; c++) s = fmaf(wa[c], B[ea * 64 + c] - B[eb * 64 + c], s);
            g_tab[idx] = s;
        } else if (idx < S_OFF) {
            int k = idx - V_OFF; int p = k / 14, i = k % 14;
            int ea = p >> 2, eb = p & 3;
            const float* wb = W + eb * 896 + i * 64;
            float s = 0.f;
            for (int c = 0; c < 64; c++) s = fmaf(wb[c], B[ea * 64 + c] - B[eb * 64 + c], s);
            g_tab[idx] = s;
        } else {
            int p = idx - S_OFF; int ea = p >> 2, eb = p & 3;
            float s = 0.f;
            for (int c = 0; c < 64; c++) {
                float d = B[ea * 64 + c] - B[eb * 64 + c];
                s = fmaf(d, d, s);
            }
            g_tab[idx] = s;
        }
    }
}

__global__ __launch_bounds__(NTHR, 1)
void main_kernel(const float* __restrict__ A, const float* __restrict__ Bv,
                 const int* __restrict__ ida, const int* __restrict__ idb, int N) {
    extern __shared__ float smem[];
    float* sTab  = smem;                        // TAB_F floats
    float* sA    = sTab + TAB_F;                // TILE*15 (row stride 15 -> conflict-free)
    float* sB    = sA + TILE * 15;              // TILE*15
    int*  sPair  = (int*)(sB + TILE * 15);      // TILE
    int*  sOrder = sPair + TILE;                // TILE
    int*  sCount = sOrder + TILE;               // 16
    int*  sStart = sCount + 16;                 // 17
    int*  sOfs   = sStart + 17;                 // 16
    int*  sChP   = sOfs + 16;                   // 64
    int*  sChO   = sChP + 64;                   // 64
    int*  sNum   = sChO + 64;                   // 1
    float* sRed  = (float*)(sNum + 1);          // NWARP

    const int tid  = threadIdx.x;
    const int lane = tid & 31;
    const int wid  = tid >> 5;

    for (int i = tid; i < TAB_F; i += NTHR) sTab[i] = g_tab[i];

    float acc = 0.f;
    const int numTiles = (N + TILE - 1) / TILE;
    for (int tile = blockIdx.x; tile < numTiles; tile += gridDim.x) {
        const int base = tile * TILE;
        const int cnt  = min(TILE, N - base);

        __syncthreads();                 // prev-tile compute done; tables ready (1st iter)
        if (tid < 16) sCount[tid] = 0;
        __syncthreads();

        // pair ids + histogram
        for (int r = tid; r < cnt; r += NTHR) {
            int p = ida[base + r] * 4 + idb[base + r];
            sPair[r] = p;
            atomicAdd(&sCount[p], 1);
        }
        // stage rows (coalesced global reads)
        for (int e = tid; e < cnt * 14; e += NTHR) {
            int r = e / 14, c = e - r * 14;
            sA[r * 15 + c] = A[(size_t)base * 14 + e];
            sB[r * 15 + c] = Bv[(size_t)base * 14 + e];
        }
        __syncthreads();

        if (tid == 0) {
            int a0 = 0;
            for (int p = 0; p < 16; p++) { sStart[p] = a0; sOfs[p] = a0; a0 += sCount[p]; }
            sStart[16] = a0;
        }
        __syncthreads();

        // scatter into pair-sorted order
        for (int r = tid; r < cnt; r += NTHR) {
            int pos = atomicAdd(&sOfs[sPair[r]], 1);
            sOrder[pos] = r;
        }
        __syncthreads();

        if (tid == 0) {
            int nc = 0;
            for (int p = 0; p < 16; p++)
                for (int o = sStart[p]; o < sStart[p + 1]; o += 32) {
                    sChP[nc] = p; sChO[nc] = o; nc++;
                }
            *sNum = nc;
        }
        __syncthreads();

        const int nChunks = *sNum;
        for (int c = wid; c < nChunks; c += NWARP) {
            const int p    = sChP[c];
            const int o    = sChO[c] + lane;
            const bool valid = o < sStart[p + 1];
            const int row  = sOrder[valid ? o : sChO[c]];

            const float* pa = sA + row * 15;
            const float* pb = sB + row * 15;
            float x[14], y[14];
#pragma unroll
            for (int i = 0; i < 14; i++) { x[i] = pa[i]; y[i] = pb[i]; }

            const ull* Gq  = (const ull*)sTab;        // 196 floats = 98 ull per table
            const ull* Gaa = Gq + ((p >> 2) * 5) * 98; // pair (ea,ea) = 5*ea
            const ull* Gbb = Gq + ((p & 3) * 5) * 98;  // pair (eb,eb) = 5*eb
            const ull* Gab = Gq + p * 98;

            float qa = quadform(Gaa, x, x);
            float qb = quadform(Gbb, y, y);
            float cr = quadform(Gab, x, y);

            const float* up = sTab + U_OFF + p * 14;
            const float* vp = sTab + V_OFF + p * 14;
            float du = 0.f, dv = 0.f;
#pragma unroll
            for (int i = 0; i < 14; i++) {
                du = fmaf(x[i], up[i], du);
                dv = fmaf(y[i], vp[i], dv);
            }
            float L = qa + qb - 2.f * cr + 2.f * du - 2.f * dv + sTab[S_OFF + p];
            acc += valid ? L : 0.f;
        }
    }

    // block reduction -> double atomic
    __syncthreads();
#pragma unroll
    for (int off = 16; off; off >>= 1) acc += __shfl_xor_sync(0xffffffffu, acc, off);
    if (lane == 0) sRed[wid] = acc;
    __syncthreads();
    if (wid == 0) {
        float v = (lane < NWARP) ? sRed[lane] : 0.f;
#pragma unroll
        for (int off = 16; off; off >>= 1) v += __shfl_xor_sync(0xffffffffu, v, off);
        if (lane == 0) atomicAdd(&g_sum, (double)v);
    }
}

__global__ void fin_kernel(float* out, long long denom) {
    if (threadIdx.x == 0) out[0] = (float)(g_sum / (double)denom);
}

// ---------------------------------------------------------------------------

extern "C" void kernel_launch(void* const* d_in, const int* in_sizes, int n_in,
                              void* d_out, int out_size) {
    const float* A    = (const float*)d_in[0];   // (N,14)
    const float* B    = (const float*)d_in[1];   // (N,14)
    const int*   ia   = (const int*)d_in[2];     // (N,)
    const int*   ib   = (const int*)d_in[3];     // (N,)
    const float* W    = (const float*)d_in[4];   // (4,14,64)
    const float* bias = (const float*)d_in[5];   // (4,64)
    const int N = in_sizes[0] / 14;

    init_kernel<<<1, 1>>>();
    prep_kernel<<<16, 256>>>(W, bias);

    size_t smemBytes = (size_t)(TAB_F + 2 * TILE * 15) * 4
                     + (size_t)(2 * TILE + 16 + 17 + 16 + 64 + 64 + 1) * 4
                     + NWARP * 4 + 64;
    cudaFuncSetAttribute(main_kernel, cudaFuncAttributeMaxDynamicSharedMemorySize,
                         (int)smemBytes);

    int sms = 148;
    cudaDeviceGetAttribute(&sms, cudaDevAttrMultiProcessorCount, 0);
    int numTiles = (N + TILE - 1) / TILE;
    int grid = numTiles < sms ? numTiles : sms;

    main_kernel<<<grid, NTHR, smemBytes>>>(A, B, ia, ib, N);
    fin_kernel<<<1, 1>>>((float*)d_out, (long long)N * 64);
}

// round 7
// speedup vs baseline: 1.1911x; 1.1911x over previous
#include <cuda_runtime.h>
#include <cstdint>

// ---------------------------------------------------------------------------
// FrameConsistencyLoss via per-pair Cholesky completion of squares.
//
// diff_row = W_ea^T a - W_eb^T b + (bias_ea - bias_eb)  (64-dim)
// L_row    = || M^T w + c ||^2,  M = [W_ea; -W_eb] (28x64), w = [a;b], c = db
//          = || C^T w + d ||^2 + s'          (C = chol(M M^T), C d = M c,
//                                             s' = c^Tc - ||d||^2)
// Diagonal pairs (ea==eb): L_row = || C14^T (a-b) ||^2   (C14 = chol(W W^T)).
//
// Main kernel: 512-row tiles, per-block 16-bucket counting sort with padded
// 32-row chunks; warps process pair-uniform chunks with broadcast table LDS
// and packed f32x2 FMA. 2 CTAs/SM.
// ---------------------------------------------------------------------------

#define TILE   512
#define NTHR   512
#define NWARP  16
#define SR     9                 // staging row stride in ull (2 floats each)
#define MAXCH  32                // max padded chunks per tile (<=31)

// table layout in floats (ull-aligned stream, consumption order)
#define OFF_BASE    0
#define OFF_STRIDE  476          // per off-diag pair: 28*(dull) + 210 C-ulls
#define DIAG_BASE   (12 * OFF_STRIDE)          // 5712
#define DIAG_STRIDE 112          // 56 ulls
#define S_BASE      (DIAG_BASE + 4 * DIAG_STRIDE)   // 6160
#define TAB_F       (S_BASE + 16)                   // 6176

__device__ float  g_tab[TAB_F];
__device__ float  g_A[16 * 28 * 28];
__device__ float  g_Mc[16 * 28];
__device__ float  g_cc[16];
__device__ double g_sum;

typedef unsigned long long ull;

__device__ __forceinline__ ull pk2(float lo, float hi) {
    ull r; asm("mov.b64 %0, {%1,%2};" : "=l"(r) : "f"(lo), "f"(hi)); return r;
}
__device__ __forceinline__ void upk2(ull v, float& lo, float& hi) {
    asm("mov.b64 {%0,%1}, %2;" : "=f"(lo), "=f"(hi) : "l"(v));
}
__device__ __forceinline__ ull ffma2(ull a, ull b, ull c) {
    ull d; asm("fma.rn.f32x2 %0, %1, %2, %3;" : "=l"(d) : "l"(a), "l"(b), "l"(c)); return d;
}
__device__ __forceinline__ ull fmul2(ull a, ull b) {
    ull d; asm("mul.rn.f32x2 %0, %1, %2;" : "=l"(d) : "l"(a), "l"(b)); return d;
}

// ---------------------------------------------------------------------------

__global__ void init_kernel() { g_sum = 0.0; }

// Stage 1: Gram matrices A[p] = M M^T (lower triangle), Mc, c^Tc.
// W: [4][14][64], B: [4][64]
__global__ void prep1_kernel(const float* __restrict__ W, const float* __restrict__ B) {
    int idx = blockIdx.x * blockDim.x + threadIdx.x;
    const int totA = 16 * 28 * 28;
    if (idx < totA) {
        int p = idx / 784, r = idx % 784, j = r / 28, k = r % 28;
        if (k > j) return;                     // lower triangle only
        int ea = p >> 2, eb = p & 3;
        const float* vj = W + ((j < 14) ? ea : eb) * 896 + ((j < 14) ? j : j - 14) * 64;
        const float* vk = W + ((k < 14) ? ea : eb) * 896 + ((k < 14) ? k : k - 14) * 64;
        float s = 0.f;
        for (int c = 0; c < 64; c++) s = fmaf(vj[c], vk[c], s);
        if ((j < 14) != (k < 14)) s = -s;
        g_A[idx] = s;
    } else if (idx < totA + 448) {
        int t = idx - totA; int p = t / 28, j = t % 28;
        int ea = p >> 2, eb = p & 3;
        const float* vj = W + ((j < 14) ? ea : eb) * 896 + ((j < 14) ? j : j - 14) * 64;
        float s = 0.f;
        for (int c = 0; c < 64; c++) s = fmaf(vj[c], B[ea * 64 + c] - B[eb * 64 + c], s);
        g_Mc[t] = (j < 14) ? s : -s;
    } else if (idx < totA + 448 + 16) {
        int p = idx - totA - 448; int ea = p >> 2, eb = p & 3;
        float s = 0.f;
        for (int c = 0; c < 64; c++) {
            float d = B[ea * 64 + c] - B[eb * 64 + c];
            s = fmaf(d, d, s);
        }
        g_cc[p] = s;
    }
}

// Stage 2: per-pair Cholesky + forward solve + pack table stream.
// One warp per pair (16 blocks x 32 threads).
__global__ void prep2_kernel() {
    __shared__ float C[28][29];
    __shared__ float dv[28];
    int p = blockIdx.x;
    int lane = threadIdx.x;
    int ea = p >> 2, eb = p & 3;
    bool diag = (ea == eb);
    int dim = diag ? 14 : 28;

    if (lane < dim)
        for (int k = 0; k <= lane; k++)
            C[lane][k] = g_A[(p * 28 + lane) * 28 + k];
    __syncwarp();

    for (int k = 0; k < dim; k++) {
        float akk = C[k][k];
        __syncwarp();
        float s = sqrtf(akk);
        float inv = 1.0f / s;
        if (lane >= k && lane < dim) C[lane][k] = (lane == k) ? s : C[lane][k] * inv;
        __syncwarp();
        if (lane > k && lane < dim) {
            float cjk = C[lane][k];
            for (int m = k + 1; m <= lane; m++) C[lane][m] -= cjk * C[m][k];
        }
        __syncwarp();
    }

    if (!diag) {
        if (lane < 28) dv[lane] = g_Mc[p * 28 + lane];
        __syncwarp();
        for (int k = 0; k < 28; k++) {
            if (lane == k) dv[k] = dv[k] / C[k][k];
            __syncwarp();
            if (lane > k && lane < 28) dv[lane] -= C[lane][k] * dv[k];
            __syncwarp();
        }
        float t = (lane < 28) ? dv[lane] * dv[lane] : 0.f;
#pragma unroll
        for (int off = 16; off; off >>= 1) t += __shfl_xor_sync(0xffffffffu, t, off);
        if (lane == 0) {
            g_tab[S_BASE + p] = g_cc[p] - t;
            float* T = g_tab + OFF_BASE + (p - p / 5 - 1) * OFF_STRIDE;
            for (int k = 0; k < 28; k++) {
                *T++ = dv[k]; *T++ = 0.f;              // (d_k, 0)
                for (int jj = k >> 1; jj < 14; jj++) {
                    int j0 = 2 * jj, j1 = 2 * jj + 1;
                    *T++ = (j0 >= k) ? C[j0][k] : 0.f; // C upper = 0
                    *T++ = C[j1][k];
                }
            }
        }
    } else {
        if (lane == 0) {
            g_tab[S_BASE + p] = 0.f;
            float* T = g_tab + DIAG_BASE + (p / 5) * DIAG_STRIDE;
            for (int k = 0; k < 14; k++)
                for (int jj = k >> 1; jj < 7; jj++) {
                    int j0 = 2 * jj, j1 = 2 * jj + 1;
                    *T++ = (j0 >= k) ? C[j0][k] : 0.f;
                    *T++ = C[j1][k];
                }
        }
    }
}

// ---------------------------------------------------------------------------

__global__ __launch_bounds__(NTHR, 2)
void main_kernel(const float* __restrict__ A, const float* __restrict__ Bv,
                 const int* __restrict__ ida, const int* __restrict__ idb, int N) {
    extern __shared__ char smemraw[];
    float* sTab      = (float*)smemraw;                       // TAB_F
    ull*   sA2       = (ull*)(smemraw + TAB_F * 4);           // TILE*SR
    ull*   sB2       = sA2 + TILE * SR;                       // TILE*SR
    int*   sOrder    = (int*)(sB2 + TILE * SR);               // MAXCH*32
    int*   sPair     = sOrder + MAXCH * 32;                   // TILE
    int*   sCount    = sPair + TILE;                          // 16
    int*   sOfs      = sCount + 16;                           // 16
    int*   sChunkP   = sOfs + 16;                             // MAXCH
    int*   sNumCh    = sChunkP + MAXCH;                       // 1
    float* sRed      = (float*)(sNumCh + 1);                  // NWARP

    const int tid = threadIdx.x, lane = tid & 31, wid = tid >> 5;

    for (int i = tid; i < TAB_F; i += NTHR) sTab[i] = g_tab[i];

    const ull neg2 = pk2(-1.f, -1.f);
    float acc = 0.f;
    const int numTiles = (N + TILE - 1) / TILE;

    for (int tile = blockIdx.x; tile < numTiles; tile += gridDim.x) {
        const int base = tile * TILE;
        const int cnt  = min(TILE, N - base);

        __syncthreads();                      // prev compute done / tab ready
        if (tid < 16) sCount[tid] = 0;
        for (int i = tid; i < MAXCH * 32; i += NTHR) sOrder[i] = -1;
        __syncthreads();

        // histogram + staging (coalesced 8B loads)
        for (int r = tid; r < cnt; r += NTHR) {
            int p = ida[base + r] * 4 + idb[base + r];
            sPair[r] = p;
            atomicAdd(&sCount[p], 1);
        }
        {
            const ull* Ag = (const ull*)A + (size_t)base * 7;
            const ull* Bg = (const ull*)Bv + (size_t)base * 7;
            for (int e = tid; e < cnt * 7; e += NTHR) {
                int r = e / 7, j = e - r * 7;
                sA2[r * SR + j] = Ag[e];
                sB2[r * SR + j] = Bg[e];
            }
        }
        __syncthreads();

        // warp 0: padded-chunk prefix scan + chunk->pair map
        if (wid == 0) {
            int c16 = (lane < 16) ? sCount[lane] : 0;
            int nch = (c16 + 31) >> 5;
            int x = nch;
#pragma unroll
            for (int d = 1; d < 16; d <<= 1) {
                int y = __shfl_up_sync(0xffffffffu, x, d);
                if (lane >= d) x += y;
            }
            int excl = x - nch;
            if (lane < 16) {
                sOfs[lane] = excl * 32;
                for (int c = 0; c < nch; c++) sChunkP[excl + c] = lane;
            }
            if (lane == 15) *sNumCh = x;
        }
        __syncthreads();

        // scatter into padded pair-sorted order
        for (int r = tid; r < cnt; r += NTHR) {
            int pos = atomicAdd(&sOfs[sPair[r]], 1);
            sOrder[pos] = r;
        }
        __syncthreads();

        // compute: pair-uniform 32-row chunks
        const int nCh = *sNumCh;
        for (int c = wid; c < nCh; c += NWARP) {
            const int p   = sChunkP[c];
            const int rid = sOrder[c * 32 + lane];
            const bool valid = rid >= 0;
            const int r = valid ? rid : 0;
            const ull* ra = sA2 + r * SR;
            const ull* rb = sB2 + r * SR;
            float L;

            if (p % 5 == 0) {
                // diagonal pair: L = ||C14^T (a-b)||^2
                const ull* T = (const ull*)(sTab + DIAG_BASE) + (p / 5) * (DIAG_STRIDE / 2);
                ull u[7];
#pragma unroll
                for (int j = 0; j < 7; j++) u[j] = ffma2(rb[j], neg2, ra[j]);
                float res = 0.f;
#pragma unroll
                for (int k = 0; k < 14; k++) {
                    ull t0 = fmul2(*T++, u[k >> 1]);
#pragma unroll
                    for (int jj = (k >> 1) + 1; jj < 7; jj++)
                        t0 = ffma2(*T++, u[jj], t0);
                    float lo, hi; upk2(t0, lo, hi);
                    float s = lo + hi;
                    res = fmaf(s, s, res);
                }
                L = res;
            } else {
                // off-diagonal: L = ||C^T w + d||^2 + s'
                const int slot = p - p / 5 - 1;
                const ull* T = (const ull*)(sTab + OFF_BASE) + (size_t)slot * (OFF_STRIDE / 2);
                ull w[14];
#pragma unroll
                for (int j = 0; j < 7; j++) { w[j] = ra[j]; w[7 + j] = rb[j]; }
                float res = 0.f;
#pragma unroll
                for (int k = 0; k < 28; k++) {
                    ull t0 = *T++;                       // (d_k, 0)
#pragma unroll
                    for (int jj = k >> 1; jj < 14; jj++)
                        t0 = ffma2(*T++, w[jj], t0);
                    float lo, hi; upk2(t0, lo, hi);
                    float s = lo + hi;
                    res = fmaf(s, s, res);
                }
                L = res + sTab[S_BASE + p];
            }
            acc += valid ? L : 0.f;
        }
    }

    // reduction -> double atomic
    __syncthreads();
#pragma unroll
    for (int off = 16; off; off >>= 1) acc += __shfl_xor_sync(0xffffffffu, acc, off);
    if (lane == 0) sRed[wid] = acc;
    __syncthreads();
    if (wid == 0) {
        float v = (lane < NWARP) ? sRed[lane] : 0.f;
#pragma unroll
        for (int off = 16; off; off >>= 1) v += __shfl_xor_sync(0xffffffffu, v, off);
        if (lane == 0) atomicAdd(&g_sum, (double)v);
    }
}

__global__ void fin_kernel(float* out, long long denom) {
    if (threadIdx.x == 0) out[0] = (float)(g_sum / (double)denom);
}

// ---------------------------------------------------------------------------

extern "C" void kernel_launch(void* const* d_in, const int* in_sizes, int n_in,
                              void* d_out, int out_size) {
    const float* A    = (const float*)d_in[0];   // (N,14)
    const float* B    = (const float*)d_in[1];   // (N,14)
    const int*   ia   = (const int*)d_in[2];     // (N,)
    const int*   ib   = (const int*)d_in[3];     // (N,)
    const float* W    = (const float*)d_in[4];   // (4,14,64)
    const float* bias = (const float*)d_in[5];   // (4,64)
    const int N = in_sizes[0] / 14;

    init_kernel<<<1, 1>>>();
    prep1_kernel<<<51, 256>>>(W, bias);
    prep2_kernel<<<16, 32>>>();

    size_t smemBytes = (size_t)TAB_F * 4
                     + (size_t)2 * TILE * SR * 8
                     + (size_t)(MAXCH * 32 + TILE + 16 + 16 + MAXCH + 1) * 4
                     + NWARP * 4 + 32;
    cudaFuncSetAttribute(main_kernel, cudaFuncAttributeMaxDynamicSharedMemorySize,
                         (int)smemBytes);

    int sms = 148;
    cudaDeviceGetAttribute(&sms, cudaDevAttrMultiProcessorCount, 0);
    int numTiles = (N + TILE - 1) / TILE;
    int grid = numTiles < 2 * sms ? numTiles : 2 * sms;

    main_kernel<<<grid, NTHR, smemBytes>>>(A, B, ia, ib, N);
    fin_kernel<<<1, 1>>>((float*)d_out, (long long)N * 64);
}

// round 9
// speedup vs baseline: 1.2744x; 1.0699x over previous
#include <cuda_runtime.h>
#include <cstdint>

// ---------------------------------------------------------------------------
// FrameConsistencyLoss via per-pair Cholesky completion of squares.
//
// L_row(off-diag) = || C^T w + d ||^2 + s'   (w = [a;b], C = chol(M M^T))
// L_row(diag)     = || C14^T (a-b) ||^2
//
// Evaluation is restructured "pack over k": S[kk] += C[j][2kk:2kk+1]*bcast(w_j)
// so one table LDS.64 feeds ffma2 for TWO row sets (fused 64-row chunks of
// one pair). Per-block 16-bucket counting sort builds the pair-uniform
// chunks. 2 CTAs/SM, 256 threads.
// ---------------------------------------------------------------------------

#define TILE   512
#define NTHR   256
#define NWARP  8
#define SR     15                // combined row stride in ull (a:0-6, b:7-13, pad)
#define MAXCH  32                // padded chunks per tile (<=31)
#define MAXW   32                // work items per tile

// table layout in ULLs:
//  [0 .. 2688)   : 12 off-diag pairs * 224 (14 d-init + 210 C)
//  [2688 .. 2912): 4 diag pairs * 56 C ulls
//  [2912 .. 2920): 16 floats s'
#define OFF_ULL   224
#define DIAG_BASE 2688
#define DIAG_ULL  56
#define SPRIME_U  2912
#define TAB_U     2920

typedef unsigned long long ull;

__device__ ull    g_tabu[TAB_U];
__device__ float  g_A[16 * 28 * 28];
__device__ float  g_Mc[16 * 28];
__device__ float  g_cc[16];
__device__ double g_sum;

__device__ __forceinline__ ull pk2(float lo, float hi) {
    ull r; asm("mov.b64 %0, {%1,%2};" : "=l"(r) : "f"(lo), "f"(hi)); return r;
}
__device__ __forceinline__ void upk2(ull v, float& lo, float& hi) {
    asm("mov.b64 {%0,%1}, %2;" : "=f"(lo), "=f"(hi) : "l"(v));
}
__device__ __forceinline__ ull ffma2(ull a, ull b, ull c) {
    ull d; asm("fma.rn.f32x2 %0, %1, %2, %3;" : "=l"(d) : "l"(a), "l"(b), "l"(c)); return d;
}

// f(j) = # table ulls in rows 0..j-1 (row m has floor(m/2)+1 ulls)
__host__ __device__ __forceinline__ int frow(int j) {
    int q = j >> 1, r = j & 1;
    return j + q * (q - 1) + r * q;
}

// ---------------------------------------------------------------------------

// Stage 1: Gram A[p] = M M^T (lower), Mc, c^Tc.  Also zeroes g_sum.
__global__ void prep1_kernel(const float* __restrict__ W, const float* __restrict__ B) {
    int idx = blockIdx.x * blockDim.x + threadIdx.x;
    if (idx == 0) g_sum = 0.0;
    const int totA = 16 * 28 * 28;
    if (idx < totA) {
        int p = idx / 784, r = idx % 784, j = r / 28, k = r % 28;
        if (k > j) return;
        int ea = p >> 2, eb = p & 3;
        const float* vj = W + ((j < 14) ? ea : eb) * 896 + ((j < 14) ? j : j - 14) * 64;
        const float* vk = W + ((k < 14) ? ea : eb) * 896 + ((k < 14) ? k : k - 14) * 64;
        float s = 0.f;
        for (int c = 0; c < 64; c++) s = fmaf(vj[c], vk[c], s);
        if ((j < 14) != (k < 14)) s = -s;
        g_A[idx] = s;
    } else if (idx < totA + 448) {
        int t = idx - totA; int p = t / 28, j = t % 28;
        int ea = p >> 2, eb = p & 3;
        const float* vj = W + ((j < 14) ? ea : eb) * 896 + ((j < 14) ? j : j - 14) * 64;
        float s = 0.f;
        for (int c = 0; c < 64; c++) s = fmaf(vj[c], B[ea * 64 + c] - B[eb * 64 + c], s);
        g_Mc[t] = (j < 14) ? s : -s;
    } else if (idx < totA + 448 + 16) {
        int p = idx - totA - 448; int ea = p >> 2, eb = p & 3;
        float s = 0.f;
        for (int c = 0; c < 64; c++) {
            float d = B[ea * 64 + c] - B[eb * 64 + c];
            s = fmaf(d, d, s);
        }
        g_cc[p] = s;
    }
}

// Stage 2: per-pair Cholesky + forward solve + parallel table packing.
__global__ void prep2_kernel() {
    __shared__ float C[28][29];
    __shared__ float dv[28];
    int p = blockIdx.x;
    int lane = threadIdx.x;
    int ea = p >> 2, eb = p & 3;
    bool diag = (ea == eb);
    int dim = diag ? 14 : 28;

    if (lane < dim)
        for (int k = 0; k <= lane; k++)
            C[lane][k] = g_A[(p * 28 + lane) * 28 + k];
    __syncwarp();

    for (int k = 0; k < dim; k++) {
        float akk = C[k][k];
        __syncwarp();
        float s = sqrtf(akk);
        float inv = 1.0f / s;
        if (lane >= k && lane < dim) C[lane][k] = (lane == k) ? s : C[lane][k] * inv;
        __syncwarp();
        if (lane > k && lane < dim) {
            float cjk = C[lane][k];
            for (int m = k + 1; m <= lane; m++) C[lane][m] -= cjk * C[m][k];
        }
        __syncwarp();
    }

    if (!diag) {
        if (lane < 28) dv[lane] = g_Mc[p * 28 + lane];
        __syncwarp();
        for (int k = 0; k < 28; k++) {
            if (lane == k) dv[k] = dv[k] / C[k][k];
            __syncwarp();
            if (lane > k && lane < 28) dv[lane] -= C[lane][k] * dv[k];
            __syncwarp();
        }
        float t = (lane < 28) ? dv[lane] * dv[lane] : 0.f;
#pragma unroll
        for (int off = 16; off; off >>= 1) t += __shfl_xor_sync(0xffffffffu, t, off);

        const int slot = p - p / 5 - 1;
        ull* T = g_tabu + slot * OFF_ULL;
        if (lane == 0) ((float*)(g_tabu + SPRIME_U))[p] = g_cc[p] - t;
        if (lane < 14) T[lane] = pk2(dv[2 * lane], dv[2 * lane + 1]);   // d-init
        if (lane < 28) {
            int q = lane >> 1;
            ull* Tj = T + 14 + frow(lane);
            for (int kk = 0; kk <= q; kk++) {
                float lo = C[lane][2 * kk];
                float hi = (2 * kk + 1 <= lane) ? C[lane][2 * kk + 1] : 0.f;
                Tj[kk] = pk2(lo, hi);
            }
        }
    } else {
        ull* T = g_tabu + DIAG_BASE + (p / 5) * DIAG_ULL;
        if (lane == 0) ((float*)(g_tabu + SPRIME_U))[p] = 0.f;
        if (lane < 14) {
            int q = lane >> 1;
            ull* Tj = T + frow(lane);
            for (int kk = 0; kk <= q; kk++) {
                float lo = C[lane][2 * kk];
                float hi = (2 * kk + 1 <= lane) ? C[lane][2 * kk + 1] : 0.f;
                Tj[kk] = pk2(lo, hi);
            }
        }
    }
}

// ---------------------------------------------------------------------------

__global__ __launch_bounds__(NTHR, 2)
void main_kernel(const float* __restrict__ A, const float* __restrict__ Bv,
                 const int* __restrict__ ida, const int* __restrict__ idb, int N) {
    extern __shared__ char smemraw[];
    ull*   sTab   = (ull*)smemraw;                      // TAB_U
    ull*   sW     = sTab + TAB_U;                       // TILE*SR
    int*   sOrder = (int*)(sW + TILE * SR);             // MAXCH*32
    int*   sPair  = sOrder + MAXCH * 32;                // TILE
    int*   sCount = sPair + TILE;                       // 16
    int*   sOfs   = sCount + 16;                        // 16
    int*   sWP    = sOfs + 16;                          // MAXW
    int*   sWO    = sWP + MAXW;                         // MAXW
    int*   sWF    = sWO + MAXW;                         // MAXW
    int*   sNum   = sWF + MAXW;                         // 1
    float* sRed   = (float*)(sNum + 1);                 // NWARP
    const float* sS = (const float*)(sTab + SPRIME_U);

    const int tid = threadIdx.x, lane = tid & 31, wid = tid >> 5;

    for (int i = tid; i < TAB_U; i += NTHR) sTab[i] = g_tabu[i];

    const ull neg1 = pk2(-1.f, -1.f);
    float acc = 0.f;
    const int numTiles = (N + TILE - 1) / TILE;

    for (int tile = blockIdx.x; tile < numTiles; tile += gridDim.x) {
        const int base = tile * TILE;
        const int cnt  = min(TILE, N - base);

        __syncthreads();                       // prev compute done / tab ready
        if (tid < 16) sCount[tid] = 0;
        for (int i = tid; i < MAXCH * 32; i += NTHR) sOrder[i] = -1;
        __syncthreads();

        // histogram + combined staging (coalesced 8B loads)
        for (int r = tid; r < cnt; r += NTHR) {
            int p = ida[base + r] * 4 + idb[base + r];
            sPair[r] = p;
            atomicAdd(&sCount[p], 1);
        }
        {
            const ull* Ag = (const ull*)A + (size_t)base * 7;
            const ull* Bg = (const ull*)Bv + (size_t)base * 7;
            for (int e = tid; e < cnt * 7; e += NTHR) {
                int r = e / 7, j = e - r * 7;
                sW[r * SR + j]     = Ag[e];
                sW[r * SR + 7 + j] = Bg[e];
            }
        }
        __syncthreads();

        // warp 0: padded prefix + work-item list (fused 64-row / single 32-row)
        if (wid == 0) {
            int c16 = (lane < 16) ? sCount[lane] : 0;
            int nch = (c16 + 31) >> 5;
            int nf = nch >> 1, ns = nch & 1;
            int nit = nf + ns;
            int xs = nch, xi = nit;
#pragma unroll
            for (int d = 1; d < 16; d <<= 1) {
                int ys = __shfl_up_sync(0xffffffffu, xs, d);
                int yi = __shfl_up_sync(0xffffffffu, xi, d);
                if (lane >= d) { xs += ys; xi += yi; }
            }
            int slotBase = (xs - nch) * 32;
            int itemBase = xi - nit;
            if (lane < 16) {
                sOfs[lane] = slotBase;
                for (int f = 0; f < nf; f++) {
                    sWP[itemBase + f] = lane;
                    sWO[itemBase + f] = slotBase + f * 64;
                    sWF[itemBase + f] = 1;
                }
                if (ns) {
                    sWP[itemBase + nf] = lane;
                    sWO[itemBase + nf] = slotBase + nf * 64;
                    sWF[itemBase + nf] = 0;
                }
            }
            if (lane == 15) *sNum = xi;
        }
        __syncthreads();

        // scatter into padded pair-sorted order
        for (int r = tid; r < cnt; r += NTHR) {
            int pos = atomicAdd(&sOfs[sPair[r]], 1);
            sOrder[pos] = r;
        }
        __syncthreads();

        // compute: each warp takes a work item (fused = 2 row sets, 1 table stream)
        const int nItems = *sNum;
        for (int it = wid; it < nItems; it += NWARP) {
            const int p     = sWP[it];
            const int off   = sWO[it];
            const int fused = sWF[it];
            const int r1 = sOrder[off + lane];
            const int r2 = fused ? sOrder[off + 32 + lane] : -1;
            const bool v1 = r1 >= 0, v2 = r2 >= 0;
            const ull* W1 = sW + (v1 ? r1 : 0) * SR;
            const ull* W2 = sW + (v2 ? r2 : (v1 ? r1 : 0)) * SR;
            float L1, L2;

            if (p % 5 == 0) {
                // diagonal pair: L = ||C14^T (a-b)||^2
                const ull* T = sTab + DIAG_BASE + (p / 5) * DIAG_ULL;
                ull u1[7], u2[7];
#pragma unroll
                for (int j = 0; j < 7; j++) {
                    u1[j] = ffma2(W1[7 + j], neg1, W1[j]);
                    u2[j] = ffma2(W2[7 + j], neg1, W2[j]);
                }
                ull S1[7], S2[7];
                const ull z = pk2(0.f, 0.f);
#pragma unroll
                for (int k = 0; k < 7; k++) { S1[k] = z; S2[k] = z; }
                int idx = 0;
#pragma unroll
                for (int jj = 0; jj < 7; jj++) {
                    float lo1, hi1, lo2, hi2;
                    upk2(u1[jj], lo1, hi1); upk2(u2[jj], lo2, hi2);
                    ull bl1 = pk2(lo1, lo1), bl2 = pk2(lo2, lo2);
                    ull bh1 = pk2(hi1, hi1), bh2 = pk2(hi2, hi2);
#pragma unroll
                    for (int kk = 0; kk <= jj; kk++) {
                        ull t = T[idx++];
                        S1[kk] = ffma2(t, bl1, S1[kk]);
                        S2[kk] = ffma2(t, bl2, S2[kk]);
                    }
#pragma unroll
                    for (int kk = 0; kk <= jj; kk++) {
                        ull t = T[idx++];
                        S1[kk] = ffma2(t, bh1, S1[kk]);
                        S2[kk] = ffma2(t, bh2, S2[kk]);
                    }
                }
                L1 = 0.f; L2 = 0.f;
#pragma unroll
                for (int k = 0; k < 7; k++) {
                    float lo, hi;
                    upk2(S1[k], lo, hi); L1 = fmaf(lo, lo, L1); L1 = fmaf(hi, hi, L1);
                    upk2(S2[k], lo, hi); L2 = fmaf(lo, lo, L2); L2 = fmaf(hi, hi, L2);
                }
            } else {
                // off-diagonal: L = ||C^T w + d||^2 + s'
                const int slot = p - p / 5 - 1;
                const ull* T = sTab + slot * OFF_ULL;
                ull S1[14], S2[14];
#pragma unroll
                for (int k = 0; k < 14; k++) { S1[k] = T[k]; S2[k] = T[k]; }
                int idx = 14;
#pragma unroll
                for (int jj = 0; jj < 14; jj++) {
                    float lo1, hi1, lo2, hi2;
                    upk2(W1[jj], lo1, hi1); upk2(W2[jj], lo2, hi2);
                    ull bl1 = pk2(lo1, lo1), bl2 = pk2(lo2, lo2);
                    ull bh1 = pk2(hi1, hi1), bh2 = pk2(hi2, hi2);
#pragma unroll
                    for (int kk = 0; kk <= jj; kk++) {
                        ull t = T[idx++];
                        S1[kk] = ffma2(t, bl1, S1[kk]);
                        S2[kk] = ffma2(t, bl2, S2[kk]);
                    }
#pragma unroll
                    for (int kk = 0; kk <= jj; kk++) {
                        ull t = T[idx++];
                        S1[kk] = ffma2(t, bh1, S1[kk]);
                        S2[kk] = ffma2(t, bh2, S2[kk]);
                    }
                }
                float sp = sS[p];
                L1 = sp; L2 = sp;
#pragma unroll
                for (int k = 0; k < 14; k++) {
                    float lo, hi;
                    upk2(S1[k], lo, hi); L1 = fmaf(lo, lo, L1); L1 = fmaf(hi, hi, L1);
                    upk2(S2[k], lo, hi); L2 = fmaf(lo, lo, L2); L2 = fmaf(hi, hi, L2);
                }
            }
            acc += (v1 ? L1 : 0.f) + (v2 ? L2 : 0.f);
        }
    }

    // reduction -> double atomic
    __syncthreads();
#pragma unroll
    for (int off = 16; off; off >>= 1) acc += __shfl_xor_sync(0xffffffffu, acc, off);
    if (lane == 0) sRed[wid] = acc;
    __syncthreads();
    if (wid == 0) {
        float v = (lane < NWARP) ? sRed[lane] : 0.f;
#pragma unroll
        for (int off = 16; off; off >>= 1) v += __shfl_xor_sync(0xffffffffu, v, off);
        if (lane == 0) atomicAdd(&g_sum, (double)v);
    }
}

__global__ void fin_kernel(float* out, long long denom) {
    if (threadIdx.x == 0) out[0] = (float)(g_sum / (double)denom);
}

// ---------------------------------------------------------------------------

extern "C" void kernel_launch(void* const* d_in, const int* in_sizes, int n_in,
                              void* d_out, int out_size) {
    const float* A    = (const float*)d_in[0];   // (N,14)
    const float* B    = (const float*)d_in[1];   // (N,14)
    const int*   ia   = (const int*)d_in[2];     // (N,)
    const int*   ib   = (const int*)d_in[3];     // (N,)
    const float* W    = (const float*)d_in[4];   // (4,14,64)
    const float* bias = (const float*)d_in[5];   // (4,64)
    const int N = in_sizes[0] / 14;

    prep1_kernel<<<51, 256>>>(W, bias);
    prep2_kernel<<<16, 32>>>();

    size_t smemBytes = (size_t)TAB_U * 8
                     + (size_t)TILE * SR * 8
                     + (size_t)(MAXCH * 32 + TILE + 16 + 16 + 3 * MAXW + 1) * 4
                     + NWARP * 4 + 32;
    cudaFuncSetAttribute(main_kernel, cudaFuncAttributeMaxDynamicSharedMemorySize,
                         (int)smemBytes);

    int sms = 148;
    cudaDeviceGetAttribute(&sms, cudaDevAttrMultiProcessorCount, 0);
    int numTiles = (N + TILE - 1) / TILE;
    int grid = numTiles < 2 * sms ? numTiles : 2 * sms;

    main_kernel<<<grid, NTHR, smemBytes>>>(A, B, ia, ib, N);
    fin_kernel<<<1, 1>>>((float*)d_out, (long long)N * 64);
}

// round 10
// speedup vs baseline: 1.6017x; 1.2568x over previous
#include <cuda_runtime.h>
#include <cstdint>

// ---------------------------------------------------------------------------
// FrameConsistencyLoss via per-pair Cholesky completion of squares, with a
// cp.async double-buffered persistent pipeline (DRAM streams continuously).
//
// L_row(off-diag) = || C^T w + d ||^2 + s'   (w = [a;b], C = chol(M M^T))
// L_row(diag)     = || C14^T (a-b) ||^2
// ---------------------------------------------------------------------------

#define TILE   512
#define NTHR   512
#define NWARP  16
#define MAXW   32

// table layout in ULLs
#define OFF_ULL   224
#define DIAG_BASE 2688
#define DIAG_ULL  56
#define SPRIME_U  2912
#define TAB_U     2920

// dynamic smem byte offsets
#define TAB_BYTES (TAB_U * 8)            // 23360
#define A_BYTES   (TILE * 56)            // 28672
#define BUF_SLOT  (2 * A_BYTES)          // 57344 (A then B)
#define BUF_OFF   TAB_BYTES
#define SORT_OFF  (BUF_OFF + 2 * BUF_SLOT)   // 138048

typedef unsigned long long ull;

__device__ ull    g_tabu[TAB_U];
__device__ double g_sum;
__device__ int    g_done;

__device__ __forceinline__ ull pk2(float lo, float hi) {
    ull r; asm("mov.b64 %0, {%1,%2};" : "=l"(r) : "f"(lo), "f"(hi)); return r;
}
__device__ __forceinline__ void upk2(ull v, float& lo, float& hi) {
    asm("mov.b64 {%0,%1}, %2;" : "=f"(lo), "=f"(hi) : "l"(v));
}
__device__ __forceinline__ ull ffma2(ull a, ull b, ull c) {
    ull d; asm("fma.rn.f32x2 %0, %1, %2, %3;" : "=l"(d) : "l"(a), "l"(b), "l"(c)); return d;
}
__device__ __forceinline__ uint32_t smem_u32(const void* p) {
    uint32_t a;
    asm("{ .reg .u64 t; cvta.to.shared.u64 t, %1; cvt.u32.u64 %0, t; }" : "=r"(a) : "l"(p));
    return a;
}
__device__ __forceinline__ void cp16(uint32_t s, const void* g) {
    asm volatile("cp.async.cg.shared.global [%0], [%1], 16;" :: "r"(s), "l"(g));
}
__device__ __forceinline__ void cp8(uint32_t s, const void* g) {
    asm volatile("cp.async.ca.shared.global [%0], [%1], 8;" :: "r"(s), "l"(g));
}

// f(j) = # table ulls in C-rows 0..j-1 (row m holds floor(m/2)+1 ulls)
__host__ __device__ __forceinline__ int frow(int j) {
    int q = j >> 1, r = j & 1;
    return j + q * (q - 1) + r * q;
}

// ---------------------------------------------------------------------------
// prep: per-pair Gram (smem) + Cholesky + solve + table pack. 16 blocks.
// ---------------------------------------------------------------------------
__global__ void prep_kernel(const float* __restrict__ W, const float* __restrict__ B) {
    __shared__ float C[28][29];
    __shared__ float dv[28];
    __shared__ float ccs[1];
    const int p = blockIdx.x, tid = threadIdx.x;
    const int ea = p >> 2, eb = p & 3;
    const bool diag = (ea == eb);
    const int dim = diag ? 14 : 28;
    if (p == 0 && tid == 0) { g_sum = 0.0; g_done = 0; }

    for (int idx = tid; idx < 784 + 28 + 1; idx += blockDim.x) {
        if (idx < 784) {
            int j = idx / 28, k = idx % 28;
            if (k <= j && j < dim) {
                const float* vj = W + ((j < 14) ? ea : eb) * 896 + ((j < 14) ? j : j - 14) * 64;
                const float* vk = W + ((k < 14) ? ea : eb) * 896 + ((k < 14) ? k : k - 14) * 64;
                float s = 0.f;
                for (int c = 0; c < 64; c++) s = fmaf(vj[c], vk[c], s);
                if ((j < 14) != (k < 14)) s = -s;
                C[j][k] = s;
            }
        } else if (idx < 812) {
            int j = idx - 784;
            if (!diag) {
                const float* vj = W + ((j < 14) ? ea : eb) * 896 + ((j < 14) ? j : j - 14) * 64;
                float s = 0.f;
                for (int c = 0; c < 64; c++)
                    s = fmaf(vj[c], B[ea * 64 + c] - B[eb * 64 + c], s);
                dv[j] = (j < 14) ? s : -s;
            }
        } else {
            if (!diag) {
                float s = 0.f;
                for (int c = 0; c < 64; c++) {
                    float d = B[ea * 64 + c] - B[eb * 64 + c];
                    s = fmaf(d, d, s);
                }
                ccs[0] = s;
            }
        }
    }
    __syncthreads();
    if (tid >= 32) return;
    const int lane = tid;

    for (int k = 0; k < dim; k++) {
        float akk = C[k][k];
        __syncwarp();
        float s = sqrtf(akk);
        float inv = 1.0f / s;
        if (lane >= k && lane < dim) C[lane][k] = (lane == k) ? s : C[lane][k] * inv;
        __syncwarp();
        if (lane > k && lane < dim) {
            float cjk = C[lane][k];
            for (int m = k + 1; m <= lane; m++) C[lane][m] -= cjk * C[m][k];
        }
        __syncwarp();
    }

    if (!diag) {
        for (int k = 0; k < 28; k++) {
            if (lane == k) dv[k] = dv[k] / C[k][k];
            __syncwarp();
            if (lane > k && lane < 28) dv[lane] -= C[lane][k] * dv[k];
            __syncwarp();
        }
        float t = (lane < 28) ? dv[lane] * dv[lane] : 0.f;
#pragma unroll
        for (int off = 16; off; off >>= 1) t += __shfl_xor_sync(0xffffffffu, t, off);

        const int slot = p - p / 5 - 1;
        ull* T = g_tabu + slot * OFF_ULL;
        if (lane == 0) ((float*)(g_tabu + SPRIME_U))[p] = ccs[0] - t;
        if (lane < 14) T[lane] = pk2(dv[2 * lane], dv[2 * lane + 1]);
        if (lane < 28) {
            int q = lane >> 1;
            ull* Tj = T + 14 + frow(lane);
            for (int kk = 0; kk <= q; kk++) {
                float lo = C[lane][2 * kk];
                float hi = (2 * kk + 1 <= lane) ? C[lane][2 * kk + 1] : 0.f;
                Tj[kk] = pk2(lo, hi);
            }
        }
    } else {
        ull* T = g_tabu + DIAG_BASE + (p / 5) * DIAG_ULL;
        if (lane == 0) ((float*)(g_tabu + SPRIME_U))[p] = 0.f;
        if (lane < 14) {
            int q = lane >> 1;
            ull* Tj = T + frow(lane);
            for (int kk = 0; kk <= q; kk++) {
                float lo = C[lane][2 * kk];
                float hi = (2 * kk + 1 <= lane) ? C[lane][2 * kk + 1] : 0.f;
                Tj[kk] = pk2(lo, hi);
            }
        }
    }
}

// ---------------------------------------------------------------------------
// evaluation (pack-over-k; fused variant shares table LDS across 2 row sets)
// ---------------------------------------------------------------------------
template<bool FUSED>
__device__ __forceinline__ float eval_off(const ull* __restrict__ T, float sp,
    const ull* __restrict__ A1, const ull* __restrict__ B1,
    const ull* __restrict__ A2, const ull* __restrict__ B2,
    bool v1, bool v2)
{
    ull S1[14], S2[14];
#pragma unroll
    for (int k = 0; k < 14; k++) { S1[k] = T[k]; if (FUSED) S2[k] = T[k]; }
    int idx = 14;
#pragma unroll
    for (int jj = 0; jj < 14; jj++) {
        ull w1 = (jj < 7) ? A1[jj] : B1[jj - 7];
        float lo1, hi1; upk2(w1, lo1, hi1);
        ull bl1 = pk2(lo1, lo1), bh1 = pk2(hi1, hi1);
        ull bl2 = 0, bh2 = 0;
        if (FUSED) {
            ull w2 = (jj < 7) ? A2[jj] : B2[jj - 7];
            float lo2, hi2; upk2(w2, lo2, hi2);
            bl2 = pk2(lo2, lo2); bh2 = pk2(hi2, hi2);
        }
#pragma unroll
        for (int kk = 0; kk <= jj; kk++) {
            ull t = T[idx + kk];
            S1[kk] = ffma2(t, bl1, S1[kk]);
            if (FUSED) S2[kk] = ffma2(t, bl2, S2[kk]);
        }
#pragma unroll
        for (int kk = 0; kk <= jj; kk++) {
            ull t = T[idx + jj + 1 + kk];
            S1[kk] = ffma2(t, bh1, S1[kk]);
            if (FUSED) S2[kk] = ffma2(t, bh2, S2[kk]);
        }
        idx += 2 * (jj + 1);
    }
    float L1 = sp, L2 = sp;
#pragma unroll
    for (int k = 0; k < 14; k++) {
        float lo, hi;
        upk2(S1[k], lo, hi); L1 = fmaf(lo, lo, L1); L1 = fmaf(hi, hi, L1);
        if (FUSED) { upk2(S2[k], lo, hi); L2 = fmaf(lo, lo, L2); L2 = fmaf(hi, hi, L2); }
    }
    float r = v1 ? L1 : 0.f;
    if (FUSED) r += v2 ? L2 : 0.f;
    return r;
}

template<bool FUSED>
__device__ __forceinline__ float eval_diag(const ull* __restrict__ T,
    const ull* __restrict__ A1, const ull* __restrict__ B1,
    const ull* __restrict__ A2, const ull* __restrict__ B2,
    bool v1, bool v2, ull neg1)
{
    ull u1[7], u2[7];
#pragma unroll
    for (int j = 0; j < 7; j++) {
        u1[j] = ffma2(B1[j], neg1, A1[j]);
        if (FUSED) u2[j] = ffma2(B2[j], neg1, A2[j]);
    }
    ull S1[7], S2[7];
    const ull z = pk2(0.f, 0.f);
#pragma unroll
    for (int k = 0; k < 7; k++) { S1[k] = z; if (FUSED) S2[k] = z; }
    int idx = 0;
#pragma unroll
    for (int jj = 0; jj < 7; jj++) {
        float lo1, hi1; upk2(u1[jj], lo1, hi1);
        ull bl1 = pk2(lo1, lo1), bh1 = pk2(hi1, hi1);
        ull bl2 = 0, bh2 = 0;
        if (FUSED) {
            float lo2, hi2; upk2(u2[jj], lo2, hi2);
            bl2 = pk2(lo2, lo2); bh2 = pk2(hi2, hi2);
        }
#pragma unroll
        for (int kk = 0; kk <= jj; kk++) {
            ull t = T[idx + kk];
            S1[kk] = ffma2(t, bl1, S1[kk]);
            if (FUSED) S2[kk] = ffma2(t, bl2, S2[kk]);
        }
#pragma unroll
        for (int kk = 0; kk <= jj; kk++) {
            ull t = T[idx + jj + 1 + kk];
            S1[kk] = ffma2(t, bh1, S1[kk]);
            if (FUSED) S2[kk] = ffma2(t, bh2, S2[kk]);
        }
        idx += 2 * (jj + 1);
    }
    float L1 = 0.f, L2 = 0.f;
#pragma unroll
    for (int k = 0; k < 7; k++) {
        float lo, hi;
        upk2(S1[k], lo, hi); L1 = fmaf(lo, lo, L1); L1 = fmaf(hi, hi, L1);
        if (FUSED) { upk2(S2[k], lo, hi); L2 = fmaf(lo, lo, L2); L2 = fmaf(hi, hi, L2); }
    }
    float r = v1 ? L1 : 0.f;
    if (FUSED) r += v2 ? L2 : 0.f;
    return r;
}

// ---------------------------------------------------------------------------

__device__ __forceinline__ void stage(uint32_t dstA, uint32_t dstB,
        const char* gA, const char* gB, int bytes, int tid) {
    const int n16 = bytes >> 4;
    for (int i = tid; i < n16; i += NTHR) {
        cp16(dstA + (i << 4), gA + ((size_t)i << 4));
        cp16(dstB + (i << 4), gB + ((size_t)i << 4));
    }
    if ((bytes & 8) && tid == 0) {
        cp8(dstA + (n16 << 4), gA + ((size_t)n16 << 4));
        cp8(dstB + (n16 << 4), gB + ((size_t)n16 << 4));
    }
}

__global__ __launch_bounds__(NTHR, 1)
void main_kernel(const float* __restrict__ A, const float* __restrict__ Bv,
                 const int* __restrict__ ida, const int* __restrict__ idb,
                 int N, float* __restrict__ out)
{
    extern __shared__ char smemraw[];
    ull*   sTab   = (ull*)smemraw;
    int*   sOrder = (int*)(smemraw + SORT_OFF);         // TILE
    int*   sCount = sOrder + TILE;                      // 16
    int*   sOfs   = sCount + 16;                        // 16
    int*   sWP    = sOfs + 16;                          // MAXW
    int*   sWO    = sWP + MAXW;                         // MAXW
    int*   sWN    = sWO + MAXW;                         // MAXW
    int*   sNum   = sWN + MAXW;                         // 1
    float* sRed   = (float*)(sNum + 1);                 // NWARP
    const float* sS = (const float*)(sTab + SPRIME_U);
    const uint32_t smem_u = smem_u32(smemraw);

    const int tid = threadIdx.x, lane = tid & 31, wid = tid >> 5;
    const int numTiles = (N + TILE - 1) / TILE;

    for (int i = tid; i < TAB_U; i += NTHR) sTab[i] = g_tabu[i];
    if (tid < 16) sCount[tid] = 0;

    int cur = 0;
    // prologue: stage first tile, load its ids
    if (blockIdx.x < numTiles) {
        int cnt = min(TILE, N - blockIdx.x * TILE);
        stage(smem_u + BUF_OFF, smem_u + BUF_OFF + A_BYTES,
              (const char*)A + (size_t)blockIdx.x * TILE * 56,
              (const char*)Bv + (size_t)blockIdx.x * TILE * 56, cnt * 56, tid);
    }
    asm volatile("cp.async.commit_group;");
    int cia = 0, cib = 0;
    {
        int g = blockIdx.x * TILE + tid;
        if (blockIdx.x < numTiles && g < N) { cia = ida[g]; cib = idb[g]; }
    }

    const ull neg1 = pk2(-1.f, -1.f);
    float acc = 0.f;

    for (int tile = blockIdx.x; tile < numTiles; tile += gridDim.x) {
        const int cnt = min(TILE, N - tile * TILE);
        asm volatile("cp.async.wait_group 0;");
        __syncthreads();                                    // B1: buffer ready, prev compute done

        // kick off next tile's copy into the other buffer (overlaps sort+compute)
        const int nxt = tile + gridDim.x;
        const int nb = cur ^ 1;
        if (nxt < numTiles) {
            int ncnt = min(TILE, N - nxt * TILE);
            stage(smem_u + BUF_OFF + nb * BUF_SLOT,
                  smem_u + BUF_OFF + nb * BUF_SLOT + A_BYTES,
                  (const char*)A + (size_t)nxt * TILE * 56,
                  (const char*)Bv + (size_t)nxt * TILE * 56, ncnt * 56, tid);
        }
        asm volatile("cp.async.commit_group;");

        const int p = cia * 4 + cib;
        const bool act = tid < cnt;
        if (act) atomicAdd(&sCount[p], 1);

        int nia = 0, nib = 0;
        if (nxt < numTiles) {
            int g = nxt * TILE + tid;
            if (g < N) { nia = ida[g]; nib = idb[g]; }
        }
        __syncthreads();                                    // B2

        if (wid == 0) {
            int n = (lane < 16) ? sCount[lane] : 0;
            int nit = (n + 63) >> 6;
            int xs = n, xi = nit;
#pragma unroll
            for (int d = 1; d < 32; d <<= 1) {
                int ys = __shfl_up_sync(0xffffffffu, xs, d);
                int yi = __shfl_up_sync(0xffffffffu, xi, d);
                if (lane >= d) { xs += ys; xi += yi; }
            }
            int rowS = xs - n, itS = xi - nit;
            if (lane < 16) {
                sOfs[lane] = rowS;
                for (int f = 0; f < nit; f++) {
                    sWP[itS + f] = lane;
                    sWO[itS + f] = rowS + f * 64;
                    sWN[itS + f] = min(64, n - f * 64);
                }
            }
            if (lane == 15) *sNum = xi;
        }
        __syncthreads();                                    // B3

        if (act) { int pos = atomicAdd(&sOfs[p], 1); sOrder[pos] = tid; }
        if (tid < 16) sCount[tid] = 0;                      // ready for next tile
        __syncthreads();                                    // B4

        const ull* bufA = (const ull*)(smemraw + BUF_OFF + cur * BUF_SLOT);
        const ull* bufB = bufA + (A_BYTES / 8);
        const int nItems = *sNum;
        for (int it = wid; it < nItems; it += NWARP) {
            const int pp = sWP[it], off = sWO[it], n = sWN[it];
            const bool v1 = lane < n;
            const bool v2 = 32 + lane < n;
            const int r1 = sOrder[off + (v1 ? lane : 0)];
            const int r2 = sOrder[off + (v2 ? 32 + lane : 0)];
            const ull* A1 = bufA + r1 * 7; const ull* B1 = bufB + r1 * 7;
            const ull* A2 = bufA + r2 * 7; const ull* B2 = bufB + r2 * 7;
            if (pp % 5 == 0) {
                const ull* T = sTab + DIAG_BASE + (pp / 5) * DIAG_ULL;
                acc += (n > 32) ? eval_diag<true >(T, A1, B1, A2, B2, v1, v2, neg1)
                                : eval_diag<false>(T, A1, B1, A1, B1, v1, false, neg1);
            } else {
                const int slot = pp - pp / 5 - 1;
                const ull* T = sTab + slot * OFF_ULL;
                const float sp = sS[pp];
                acc += (n > 32) ? eval_off<true >(T, sp, A1, B1, A2, B2, v1, v2)
                                : eval_off<false>(T, sp, A1, B1, A1, B1, v1, false);
            }
        }
        cia = nia; cib = nib; cur ^= 1;
    }

    // block reduction -> double atomic -> last CTA finalizes (no fin kernel)
    __syncthreads();
#pragma unroll
    for (int off = 16; off; off >>= 1) acc += __shfl_xor_sync(0xffffffffu, acc, off);
    if (lane == 0) sRed[wid] = acc;
    __syncthreads();
    if (wid == 0) {
        float v = (lane < NWARP) ? sRed[lane] : 0.f;
#pragma unroll
        for (int off = 16; off; off >>= 1) v += __shfl_xor_sync(0xffffffffu, v, off);
        if (lane == 0) {
            atomicAdd(&g_sum, (double)v);
            __threadfence();
            int done = atomicAdd(&g_done, 1);
            if (done == (int)gridDim.x - 1) {
                double s = *((volatile double*)&g_sum);
                out[0] = (float)(s / ((double)N * 64.0));
                g_done = 0;
            }
        }
    }
}

// ---------------------------------------------------------------------------

extern "C" void kernel_launch(void* const* d_in, const int* in_sizes, int n_in,
                              void* d_out, int out_size) {
    const float* A    = (const float*)d_in[0];   // (N,14)
    const float* B    = (const float*)d_in[1];   // (N,14)
    const int*   ia   = (const int*)d_in[2];     // (N,)
    const int*   ib   = (const int*)d_in[3];     // (N,)
    const float* W    = (const float*)d_in[4];   // (4,14,64)
    const float* bias = (const float*)d_in[5];   // (4,64)
    const int N = in_sizes[0] / 14;

    prep_kernel<<<16, 256>>>(W, bias);

    size_t smemBytes = (size_t)SORT_OFF + TILE * 4
                     + (size_t)(16 + 16 + 3 * MAXW + 1) * 4 + NWARP * 4 + 64;
    cudaFuncSetAttribute(main_kernel, cudaFuncAttributeMaxDynamicSharedMemorySize,
                         (int)smemBytes);

    int sms = 148;
    cudaDeviceGetAttribute(&sms, cudaDevAttrMultiProcessorCount, 0);
    int numTiles = (N + TILE - 1) / TILE;
    int grid = numTiles < sms ? numTiles : sms;

    main_kernel<<<grid, NTHR, smemBytes>>>(A, B, ia, ib, N, (float*)d_out);
}